// round 2
// baseline (speedup 1.0000x reference)
#include <cuda_runtime.h>
#include <cuda_bf16.h>

// NoQmix_74560632258885
//
// attention = softmax(e, axis=1) is column-stochastic (every column sums to 1,
// including fully-masked ones), so q_tot[b] = sum_j qs[b,j]. The GEMM/GAT/
// softmax pipeline is algebraically dead. Output = row-sum of agent_qs
// [4096, 64] -> [4096].
//
// R1 kernel: latency-floor optimization.
//  - Each warp handles TWO rows: lanes 0-15 -> row 2w, lanes 16-31 -> row 2w+1.
//  - Each lane does ONE LDG.128 (float4), 16 lanes x 16B = full 256B row,
//    warp reads 512B fully contiguous.
//  - 3 in-register adds + 4-step butterfly over the 16-lane half-warp.
//  - 2048 warps / 256 blocks (half of R0) -> less launch/drain spread.

static constexpr int N_AGENTS = 64;

__global__ __launch_bounds__(256, 8)
void noqmix_rowsum_kernel(const float4* __restrict__ qs4,
                          float* __restrict__ out,
                          int nbatch) {
    const int gtid    = blockIdx.x * blockDim.x + threadIdx.x;
    const int warp_id = gtid >> 5;
    const int lane    = threadIdx.x & 31;
    const int half    = lane >> 4;        // which row within the warp
    const int sub     = lane & 15;        // lane within the 16-lane group

    const int row = warp_id * 2 + half;
    if (row >= nbatch) return;

    // row = 64 floats = 16 float4; lane `sub` grabs one float4
    const float4 v4 = qs4[(long long)row * (N_AGENTS / 4) + sub];
    float v = (v4.x + v4.y) + (v4.z + v4.w);

    // butterfly over the 16-lane half-warp (xor offsets stay inside the half)
    #pragma unroll
    for (int off = 8; off > 0; off >>= 1)
        v += __shfl_xor_sync(0xFFFFFFFFu, v, off);

    if (sub == 0) out[row] = v;
}

extern "C" void kernel_launch(void* const* d_in, const int* in_sizes, int n_in,
                              void* d_out, int out_size) {
    // Input order (metadata): features, agent_qs, adj, states, W, a
    const float4* agent_qs4 = (const float4*)d_in[1];
    float* out = (float*)d_out;

    const int nbatch = in_sizes[1] / N_AGENTS;  // 4096

    const int threads = 256;                      // 8 warps -> 16 rows per block
    const int rows_per_block = (threads / 32) * 2;
    const int blocks = (nbatch + rows_per_block - 1) / rows_per_block;  // 256

    noqmix_rowsum_kernel<<<blocks, threads>>>(agent_qs4, out, nbatch);
}